// round 1
// baseline (speedup 1.0000x reference)
#include <cuda_runtime.h>
#include <math.h>
#include <stdint.h>

#define VN 9216
#define EN 18240
#define WID 96
#define B_ 8
#define NC 21
#define H0_ 384
#define NLOSSBLK 64

// ---------------- global scratch (no allocations allowed) ----------------
__device__ float g_low[B_ * 3 * VN];          // resized low feats
__device__ float g_prob[B_ * NC * VN];        // softmax
__device__ float g_AS[B_ * NC * VN];          // filtered output (AS1 then AS2)
__device__ float g_ew[16 * VN];
__device__ unsigned short g_parent16[16 * VN];
__device__ unsigned short g_order16[16 * VN];
__device__ int g_tredge[16 * VN];
__device__ int g_levelstart[16 * (VN + 2)];
__device__ int g_maxd[16];
__device__ double g_partL[NLOSSBLK];
__device__ double g_partN[NLOSSBLK];

__device__ __forceinline__ void edge_uv(int e, int& u, int& v) {
    if (e < 9120) { u = e; v = e + WID; }                 // vertical
    else { int t = e - 9120; int r = t / 95, c = t - r * 95; u = r * WID + c; v = u + 1; }  // horizontal
}

// ---------------- prep: bilinear (antialiased) resize 384->96 ----------------
__global__ void resize_kernel(const float* __restrict__ low) {
    int idx = blockIdx.x * blockDim.x + threadIdx.x;
    if (idx >= B_ * 3 * VN) return;
    int v = idx % VN;
    int bc = idx / VN;
    int oy = v / WID, ox = v - (v / WID) * WID;
    const float rw[8] = {0.125f, 0.375f, 0.625f, 0.875f, 0.875f, 0.625f, 0.375f, 0.125f};
    int iy0 = 4 * oy - 2, ix0 = 4 * ox - 2;
    float wy[8], wx[8], sy = 0.f, sx = 0.f;
#pragma unroll
    for (int j = 0; j < 8; j++) {
        int iy = iy0 + j;
        wy[j] = (iy >= 0 && iy < H0_) ? rw[j] : 0.f;
        sy += wy[j];
        int ix = ix0 + j;
        wx[j] = (ix >= 0 && ix < H0_) ? rw[j] : 0.f;
        sx += wx[j];
    }
    const float* src = low + (size_t)bc * (H0_ * H0_);
    float acc = 0.f;
#pragma unroll
    for (int j = 0; j < 8; j++) {
        if (wy[j] == 0.f) continue;
        const float* row = src + (iy0 + j) * H0_;
        float rs = 0.f;
#pragma unroll
        for (int k = 0; k < 8; k++) {
            if (wx[k] != 0.f) rs += wx[k] * row[ix0 + k];
        }
        acc += wy[j] * rs;
    }
    g_low[idx] = acc / (sy * sx);
}

// ---------------- prep: softmax over 21 classes ----------------
__global__ void softmax_kernel(const float* __restrict__ preds) {
    int idx = blockIdx.x * blockDim.x + threadIdx.x;
    if (idx >= B_ * VN) return;
    int b = idx / VN, v = idx - (idx / VN) * VN;
    const float* p = preds + (size_t)b * NC * VN + v;
    float vals[NC];
    float m = -3.4e38f;
#pragma unroll
    for (int c = 0; c < NC; c++) { vals[c] = p[(size_t)c * VN]; m = fmaxf(m, vals[c]); }
    float s = 0.f;
#pragma unroll
    for (int c = 0; c < NC; c++) { vals[c] = expf(vals[c] - m); s += vals[c]; }
    float inv = 1.f / s;
    float* o = g_prob + (size_t)b * NC * VN + v;
#pragma unroll
    for (int c = 0; c < NC; c++) o[(size_t)c * VN] = vals[c] * inv;
}

// ---------------- tree build: Boruvka MST + BFS rooting + levels + ew ----------------
// smem layout (union across phases):
//   [0, 73728)          : bestS (u64[VN])      | phase BFS: depthS(int[VN]) + parentS(int[VN])
//   [73728, 146688)     : wS (float[EN])       | phase ew : accS(float[VN]) (fits)
//   [146688, 183552)    : compS (int[VN])      | cursorS
//   [183552, 220416)    : linkS (int[VN])      | countS
#define BUILD_SMEM 220416

extern "C" __global__ void __launch_bounds__(1024, 1)
build_kernel(const float* __restrict__ high) {
    extern __shared__ unsigned char smemRaw[];
    int t = blockIdx.x;
    int b = t >> 1, f = t & 1;
    const float* embed = f ? (high + (size_t)b * 256 * VN) : ((const float*)g_low + (size_t)b * 3 * VN);
    int C = f ? 256 : 3;

    unsigned long long* bestS = (unsigned long long*)smemRaw;
    float* wS = (float*)(smemRaw + 73728);
    int* compS = (int*)(smemRaw + 146688);
    int* linkS = (int*)(smemRaw + 183552);
    int* depthS = (int*)smemRaw;
    int* parentS = ((int*)smemRaw) + VN;
    int* cursorS = compS;
    int* countS = linkS;
    float* accS = wS;

    __shared__ int sFlag, sCnt;
    int tid = threadIdx.x;
    const int NT = 1024;

    // 1. edge weights
    {
        float acc[18];
#pragma unroll
        for (int k = 0; k < 18; k++) acc[k] = 0.f;
        for (int c = 0; c < C; c++) {
            const float* p = embed + (size_t)c * VN;
#pragma unroll
            for (int k = 0; k < 18; k++) {
                int e = tid + k * NT;
                if (e < EN) {
                    int u, v; edge_uv(e, u, v);
                    float d = p[u] - p[v];
                    acc[k] += d * d;
                }
            }
        }
#pragma unroll
        for (int k = 0; k < 18; k++) {
            int e = tid + k * NT;
            if (e < EN) wS[e] = acc[k];
        }
    }
    for (int v = tid; v < VN; v += NT) compS[v] = v;
    if (tid == 0) sCnt = 0;
    __syncthreads();

    // 2. Boruvka (keys (w_bits, edge_idx) -> identical tree to stable Kruskal)
    for (int round = 0; round < 20; ++round) {
        for (int v = tid; v < VN; v += NT) bestS[v] = ~0ull;
        if (tid == 0) sFlag = 0;
        __syncthreads();
        for (int e = tid; e < EN; e += NT) {
            int u, v; edge_uv(e, u, v);
            int cu = compS[u], cv = compS[v];
            if (cu != cv) {
                unsigned long long key = ((unsigned long long)__float_as_uint(wS[e]) << 32) | (unsigned)e;
                atomicMin(&bestS[cu], key);
                atomicMin(&bestS[cv], key);
                sFlag = 1;
            }
        }
        __syncthreads();
        if (!sFlag) break;
        // link + record tree edges (dedup: mutual pair recorded by smaller root)
        for (int v = tid; v < VN; v += NT) {
            unsigned long long bkey = bestS[v];
            int nl = v;
            if (bkey != ~0ull) {
                int e = (int)(bkey & 0xffffffffu);
                int u0, v0; edge_uv(e, u0, v0);
                int cu = compS[u0], cv = compS[v0];
                int d = (cu == v) ? cv : cu;
                nl = d;
                if (bestS[d] != bkey || v < d) {
                    int p = atomicAdd(&sCnt, 1);
                    g_tredge[t * VN + p] = e;
                }
            }
            linkS[v] = nl;
        }
        __syncthreads();
        // break 2-cycles (two-phase)
        {
            int nl[9]; int ki = 0;
            for (int v = tid; v < VN; v += NT, ++ki) {
                int l = linkS[v];
                nl[ki] = (l != v && linkS[l] == v && v < l) ? v : l;
            }
            __syncthreads();
            ki = 0;
            for (int v = tid; v < VN; v += NT, ++ki) linkS[v] = nl[ki];
            __syncthreads();
        }
        // pointer jumping
        for (int it = 0; it < 14; ++it) {
            int nl[9]; int ki = 0;
            for (int v = tid; v < VN; v += NT, ++ki) nl[ki] = linkS[linkS[v]];
            __syncthreads();
            ki = 0;
            for (int v = tid; v < VN; v += NT, ++ki) linkS[v] = nl[ki];
            __syncthreads();
        }
        for (int v = tid; v < VN; v += NT) compS[v] = linkS[compS[v]];
        __syncthreads();
    }
    __syncthreads();
    int nTree = sCnt;

    // 3. BFS rooting (level-synchronous; unique discoverer in a tree -> deterministic)
    for (int v = tid; v < VN; v += NT) { depthS[v] = -1; parentS[v] = 0; }
    __syncthreads();
    if (tid == 0) depthS[0] = 0;
    __syncthreads();
    int level = 0;
    while (true) {
        if (tid == 0) sFlag = 0;
        __syncthreads();
        for (int i = tid; i < nTree; i += NT) {
            int e = g_tredge[t * VN + i];
            int u, v; edge_uv(e, u, v);
            int du = depthS[u], dv = depthS[v];
            if (du == level && dv < 0) { depthS[v] = level + 1; parentS[v] = u; sFlag = 1; }
            else if (dv == level && du < 0) { depthS[u] = level + 1; parentS[u] = v; sFlag = 1; }
        }
        __syncthreads();
        if (!sFlag) break;
        level++;
    }
    int maxd = level;
    if (tid == 0) g_maxd[t] = maxd;

    // 4. level histogram + order + parent export
    for (int d = tid; d <= maxd; d += NT) countS[d] = 0;
    __syncthreads();
    for (int v = tid; v < VN; v += NT) atomicAdd(&countS[depthS[v]], 1);
    __syncthreads();
    if (tid == 0) {
        int run = 0;
        int* ls = g_levelstart + t * (VN + 2);
        for (int d = 0; d <= maxd; ++d) { ls[d] = run; cursorS[d] = run; run += countS[d]; }
        ls[maxd + 1] = run;
    }
    __syncthreads();
    for (int v = tid; v < VN; v += NT) {
        int pos = atomicAdd(&cursorS[depthS[v]], 1);
        g_order16[t * VN + pos] = (unsigned short)v;
        g_parent16[t * VN + v] = (unsigned short)parentS[v];
    }
    __syncthreads();

    // 5. ew = exp(-||emb[v]-emb[parent]||^2 / 2), root -> 0
    for (int v = tid; v < VN; v += NT) accS[v] = 0.f;
    __syncthreads();
    for (int c = 0; c < C; ++c) {
        const float* p = embed + (size_t)c * VN;
        for (int v = tid; v < VN; v += NT) {
            float d = p[v] - p[parentS[v]];
            accS[v] += d * d;
        }
    }
    __syncthreads();
    for (int v = tid; v < VN; v += NT)
        g_ew[t * VN + v] = (v == 0) ? 0.f : expf(-accS[v] * 0.5f);
}

// ---------------- tree-filter sweep: 3 data channels + ones channel per block ----------------
// smem: buf float[VN*4] (147456) | ewS float[VN] (36864) | parS u16[VN] (18432) | ordS u16[VN] (18432)
#define SWEEP_SMEM 221184

extern "C" __global__ void __launch_bounds__(256, 1)
sweep_kernel(int f) {
    extern __shared__ unsigned char sm[];
    int g = blockIdx.x;          // channel group 0..6 -> channels 3g..3g+2
    int b = blockIdx.y;          // sample
    int t = b * 2 + f;
    float* buf = (float*)sm;
    float* ewS = (float*)(sm + 147456);
    unsigned short* parS = (unsigned short*)(sm + 147456 + 36864);
    unsigned short* ordS = (unsigned short*)(sm + 147456 + 36864 + 18432);
    int tid = threadIdx.x;
    const int NT = 256;

    for (int v = tid; v < VN; v += NT) {
        ewS[v] = g_ew[t * VN + v];
        parS[v] = g_parent16[t * VN + v];
        ordS[v] = g_order16[t * VN + v];
    }
    const float* in = (f == 0) ? g_prob : g_AS;
    const float* inb = in + (size_t)b * NC * VN;
    for (int c = 0; c < 3; c++) {
        const float* p = inb + (size_t)(g * 3 + c) * VN;
        for (int v = tid; v < VN; v += NT) buf[v * 4 + c] = p[v];
    }
    for (int v = tid; v < VN; v += NT) buf[v * 4 + 3] = 1.f;
    __syncthreads();

    int maxd = g_maxd[t];
    const int* ls = g_levelstart + t * (VN + 2);

    // up sweep (pull from children): deepest-1 .. 0
    for (int d = maxd - 1; d >= 0; --d) {
        int s = ls[d], e = ls[d + 1];
        int n = (e - s) << 2;
        for (int i = tid; i < n; i += NT) {
            int u = ordS[s + (i >> 2)];
            int c = i & 3;
            float acc = buf[u * 4 + c];
            int col = u - (u / WID) * WID;
            int n2;
            if (u >= WID) { n2 = u - WID; if (parS[n2] == u) acc += ewS[n2] * buf[n2 * 4 + c]; }
            if (u < VN - WID) { n2 = u + WID; if (parS[n2] == u) acc += ewS[n2] * buf[n2 * 4 + c]; }
            if (col > 0) { n2 = u - 1; if (parS[n2] == u) acc += ewS[n2] * buf[n2 * 4 + c]; }
            if (col < WID - 1) { n2 = u + 1; if (parS[n2] == u) acc += ewS[n2] * buf[n2 * 4 + c]; }
            buf[u * 4 + c] = acc;
        }
        __syncthreads();
    }
    // down sweep (in place): 1 .. maxd
    for (int d = 1; d <= maxd; ++d) {
        int s = ls[d], e = ls[d + 1];
        int n = (e - s) << 2;
        for (int i = tid; i < n; i += NT) {
            int v = ordS[s + (i >> 2)];
            int c = i & 3;
            float w = ewS[v];
            buf[v * 4 + c] = w * buf[(int)parS[v] * 4 + c] + (1.f - w * w) * buf[v * 4 + c];
        }
        __syncthreads();
    }
    // normalize by the ones channel, write out
    float* outb = g_AS + (size_t)b * NC * VN;
    for (int c = 0; c < 3; c++) {
        float* p = outb + (size_t)(g * 3 + c) * VN;
        for (int v = tid; v < VN; v += NT) p[v] = buf[v * 4 + c] / buf[v * 4 + 3];
    }
}

// ---------------- loss: deterministic two-stage reduction ----------------
__global__ void loss_part_kernel(const int* __restrict__ roi) {
    __shared__ double sL[256];
    __shared__ double sN[256];
    int tid = threadIdx.x, blk = blockIdx.x;
    const int total = B_ * NC * VN;
    double aL = 0.0, aN = 0.0;
    for (int idx = blk * 256 + tid; idx < total; idx += NLOSSBLK * 256) {
        int b = idx / (NC * VN);
        int r = idx - b * (NC * VN);
        int c = r / VN;
        int v = r - c * VN;
        int y = v / WID, x = v - y * WID;
        float rv = (float)roi[(size_t)b * (H0_ * H0_) + (y * 4) * H0_ + x * 4];
        aL += (double)(rv * fabsf(g_prob[idx] - g_AS[idx]));
        if (c == 0) aN += (double)rv;
    }
    sL[tid] = aL; sN[tid] = aN;
    __syncthreads();
    for (int s = 128; s > 0; s >>= 1) {
        if (tid < s) { sL[tid] += sL[tid + s]; sN[tid] += sN[tid + s]; }
        __syncthreads();
    }
    if (tid == 0) { g_partL[blk] = sL[0]; g_partN[blk] = sN[0]; }
}

__global__ void loss_final_kernel(float* out) {
    if (threadIdx.x == 0 && blockIdx.x == 0) {
        double L = 0.0, N = 0.0;
        for (int i = 0; i < NLOSSBLK; i++) { L += g_partL[i]; N += g_partN[i]; }
        double res = (N > 0.0) ? L / ((N > 1.0) ? N : 1.0) : L;
        out[0] = (float)(0.4 * res);
    }
}

// ---------------- launch ----------------
extern "C" void kernel_launch(void* const* d_in, const int* in_sizes, int n_in,
                              void* d_out, int out_size) {
    (void)in_sizes; (void)n_in; (void)out_size;
    const float* preds = (const float*)d_in[0];
    const float* low = (const float*)d_in[1];
    const float* high = (const float*)d_in[2];
    const int* roi = (const int*)d_in[3];
    float* out = (float*)d_out;

    cudaFuncSetAttribute(build_kernel, cudaFuncAttributeMaxDynamicSharedMemorySize, BUILD_SMEM);
    cudaFuncSetAttribute(sweep_kernel, cudaFuncAttributeMaxDynamicSharedMemorySize, SWEEP_SMEM);

    resize_kernel<<<(B_ * 3 * VN + 255) / 256, 256>>>(low);
    softmax_kernel<<<(B_ * VN + 255) / 256, 256>>>(preds);
    build_kernel<<<16, 1024, BUILD_SMEM>>>(high);
    dim3 gs(7, B_);
    sweep_kernel<<<gs, 256, SWEEP_SMEM>>>(0);
    sweep_kernel<<<gs, 256, SWEEP_SMEM>>>(1);
    loss_part_kernel<<<NLOSSBLK, 256>>>(roi);
    loss_final_kernel<<<1, 1>>>(out);
}

// round 2
// speedup vs baseline: 2.1781x; 2.1781x over previous
#include <cuda_runtime.h>
#include <math.h>
#include <stdint.h>

#define VN 9216
#define EN 18240
#define WID 96
#define B_ 8
#define NC 21
#define H0_ 384
#define NLOSSBLK 64

// ---------------- global scratch ----------------
__device__ __align__(16) float g_low[B_ * 3 * VN];
__device__ float g_prob[B_ * NC * VN];
__device__ float g_AS[B_ * NC * VN];
__device__ float g_ew[16 * VN];               // indexed by node
__device__ unsigned g_ord32[16 * VN];         // rank -> v | childmask<<14 | pardir<<18
__device__ int g_tredge[16 * VN];
__device__ int g_levelstart[16 * 2048];
__device__ int g_maxd[16];
__device__ double g_partL[NLOSSBLK];
__device__ double g_partN[NLOSSBLK];

__constant__ int c_off[4] = {-WID, WID, -1, 1};

__device__ __forceinline__ void edge_uv(int e, int& u, int& v) {
    if (e < 9120) { u = e; v = e + WID; }
    else { int t = e - 9120; int r = t / 95, c = t - r * 95; u = r * WID + c; v = u + 1; }
}

// ---------------- prep: antialiased bilinear resize 384->96 ----------------
__global__ void resize_kernel(const float* __restrict__ low) {
    int idx = blockIdx.x * blockDim.x + threadIdx.x;
    if (idx >= B_ * 3 * VN) return;
    int v = idx % VN;
    int bc = idx / VN;
    int oy = v / WID, ox = v - (v / WID) * WID;
    const float rw[8] = {0.125f, 0.375f, 0.625f, 0.875f, 0.875f, 0.625f, 0.375f, 0.125f};
    int iy0 = 4 * oy - 2, ix0 = 4 * ox - 2;
    float wy[8], wx[8], sy = 0.f, sx = 0.f;
#pragma unroll
    for (int j = 0; j < 8; j++) {
        int iy = iy0 + j;
        wy[j] = (iy >= 0 && iy < H0_) ? rw[j] : 0.f;
        sy += wy[j];
        int ix = ix0 + j;
        wx[j] = (ix >= 0 && ix < H0_) ? rw[j] : 0.f;
        sx += wx[j];
    }
    const float* src = low + (size_t)bc * (H0_ * H0_);
    float acc = 0.f;
#pragma unroll
    for (int j = 0; j < 8; j++) {
        if (wy[j] == 0.f) continue;
        const float* row = src + (iy0 + j) * H0_;
        float rs = 0.f;
#pragma unroll
        for (int k = 0; k < 8; k++) {
            if (wx[k] != 0.f) rs += wx[k] * row[ix0 + k];
        }
        acc += wy[j] * rs;
    }
    g_low[idx] = acc / (sy * sx);
}

// ---------------- prep: softmax ----------------
__global__ void softmax_kernel(const float* __restrict__ preds) {
    int idx = blockIdx.x * blockDim.x + threadIdx.x;
    if (idx >= B_ * VN) return;
    int b = idx / VN, v = idx - (idx / VN) * VN;
    const float* p = preds + (size_t)b * NC * VN + v;
    float vals[NC];
    float m = -3.4e38f;
#pragma unroll
    for (int c = 0; c < NC; c++) { vals[c] = p[(size_t)c * VN]; m = fmaxf(m, vals[c]); }
    float s = 0.f;
#pragma unroll
    for (int c = 0; c < NC; c++) { vals[c] = expf(vals[c] - m); s += vals[c]; }
    float inv = 1.f / s;
    float* o = g_prob + (size_t)b * NC * VN + v;
#pragma unroll
    for (int c = 0; c < NC; c++) o[(size_t)c * VN] = vals[c] * inv;
}

// ---------------- tree build ----------------
// smem layout:
//   [0,73728)        bestS u64[VN]      | post-Boruvka: orderS u16[VN] @0, parS u16[VN] @18432
//   [73728,146688)   wS float[EN]       (kept alive until export: ew derives from it)
//   [146688,183552)  compS int[VN]      | post: lsS int[2048]
//   [183552,220416)  linkS int[VN]      | post: adjS int[VN]
#define BUILD_SMEM 220416

extern "C" __global__ void __launch_bounds__(1024, 1)
build_kernel(const float* __restrict__ high) {
    extern __shared__ unsigned char sm[];
    int t = blockIdx.x;
    int b = t >> 1, f = t & 1;
    const float* embed = f ? (high + (size_t)b * 256 * VN) : ((const float*)g_low + (size_t)b * 3 * VN);
    int C = f ? 256 : 3;

    unsigned long long* bestS = (unsigned long long*)sm;
    float* wS = (float*)(sm + 73728);
    int* compS = (int*)(sm + 146688);
    int* linkS = (int*)(sm + 183552);
    unsigned short* orderS = (unsigned short*)sm;
    unsigned short* parS = (unsigned short*)(sm + 18432);
    int* lsS = (int*)(sm + 146688);
    int* adjS = (int*)(sm + 183552);

    __shared__ int sFlag, sCnt, sCur, sJ[2];
    int tid = threadIdx.x;
    const int NT = 1024;

    // ---- 1. edge weights: 3-row bands with float4 loads ----
    if (tid < 768) {
        int t0 = tid % 24, band = tid / 24;
        int c0 = t0 * 4, r0 = band * 3;
        bool hasR3 = (band < 31);
        bool hasS = (t0 < 23);
        float aV[3][4], aH[3][4];
#pragma unroll
        for (int j = 0; j < 3; j++)
#pragma unroll
            for (int k = 0; k < 4; k++) { aV[j][k] = 0.f; aH[j][k] = 0.f; }
        for (int c = 0; c < C; ++c) {
            const float* pf = embed + (size_t)c * VN;
            const float4* p4 = (const float4*)pf;
            float4 q0 = p4[(r0 + 0) * 24 + t0];
            float4 q1 = p4[(r0 + 1) * 24 + t0];
            float4 q2 = p4[(r0 + 2) * 24 + t0];
            float4 q3 = hasR3 ? p4[(r0 + 3) * 24 + t0] : make_float4(0.f, 0.f, 0.f, 0.f);
            float rr[4][4];
            rr[0][0]=q0.x; rr[0][1]=q0.y; rr[0][2]=q0.z; rr[0][3]=q0.w;
            rr[1][0]=q1.x; rr[1][1]=q1.y; rr[1][2]=q1.z; rr[1][3]=q1.w;
            rr[2][0]=q2.x; rr[2][1]=q2.y; rr[2][2]=q2.z; rr[2][3]=q2.w;
            rr[3][0]=q3.x; rr[3][1]=q3.y; rr[3][2]=q3.z; rr[3][3]=q3.w;
            float s0 = 0.f, s1 = 0.f, s2 = 0.f;
            if (hasS) {
                s0 = pf[(r0 + 0) * WID + c0 + 4];
                s1 = pf[(r0 + 1) * WID + c0 + 4];
                s2 = pf[(r0 + 2) * WID + c0 + 4];
            }
            float ss[3] = {s0, s1, s2};
#pragma unroll
            for (int j = 0; j < 3; j++) {
#pragma unroll
                for (int k = 0; k < 4; k++) {
                    float dv = rr[j][k] - rr[j + 1][k];
                    aV[j][k] += dv * dv;
                }
#pragma unroll
                for (int k = 0; k < 3; k++) {
                    float dh = rr[j][k] - rr[j][k + 1];
                    aH[j][k] += dh * dh;
                }
                if (hasS) { float dh = rr[j][3] - ss[j]; aH[j][3] += dh * dh; }
            }
        }
#pragma unroll
        for (int j = 0; j < 3; j++) {
            int r = r0 + j;
            if (r < 95) {
#pragma unroll
                for (int k = 0; k < 4; k++) wS[r * WID + c0 + k] = aV[j][k];
            }
            int hb = 9120 + r * 95 + c0;
            wS[hb + 0] = aH[j][0]; wS[hb + 1] = aH[j][1]; wS[hb + 2] = aH[j][2];
            if (hasS) wS[hb + 3] = aH[j][3];
        }
    }
    for (int v = tid; v < VN; v += NT) compS[v] = v;
    if (tid == 0) sCnt = 0;
    __syncthreads();

    // ---- 2. Boruvka ((w_bits, e) keys == stable-Kruskal tree) ----
    for (int round = 0; round < 20; ++round) {
        for (int v = tid; v < VN; v += NT) bestS[v] = ~0ull;
        if (tid == 0) sFlag = 0;
        __syncthreads();
        for (int e = tid; e < EN; e += NT) {
            int u, v; edge_uv(e, u, v);
            int cu = compS[u], cv = compS[v];
            if (cu != cv) {
                unsigned long long key = ((unsigned long long)__float_as_uint(wS[e]) << 32) | (unsigned)e;
                atomicMin(&bestS[cu], key);
                atomicMin(&bestS[cv], key);
                sFlag = 1;
            }
        }
        __syncthreads();
        if (!sFlag) break;
        for (int v = tid; v < VN; v += NT) {
            unsigned long long bk = bestS[v];
            int nl = v;
            if (bk != ~0ull) {
                int e = (int)(bk & 0xffffffffu);
                int u0, v0; edge_uv(e, u0, v0);
                int cu = compS[u0], cv = compS[v0];
                int d = (cu == v) ? cv : cu;
                nl = d;
                if (bestS[d] != bk || v < d) {
                    int p = atomicAdd(&sCnt, 1);
                    g_tredge[t * VN + p] = e;
                }
            }
            linkS[v] = nl;
        }
        __syncthreads();
        {   // break 2-cycles
            int nl[9]; int ki = 0;
            for (int v = tid; v < VN; v += NT, ++ki) {
                int l = linkS[v];
                nl[ki] = (l != v && linkS[l] == v && v < l) ? v : l;
            }
            __syncthreads();
            ki = 0;
            for (int v = tid; v < VN; v += NT, ++ki) linkS[v] = nl[ki];
            if (tid == 0) { sJ[0] = 0; sJ[1] = 0; }
            __syncthreads();
        }
        // pointer jumping with convergence early-exit
        for (int it = 0; it < 14; ++it) {
            int p = it & 1;
            int nl[9]; int ki = 0; int ch = 0;
            for (int v = tid; v < VN; v += NT, ++ki) {
                int l = linkS[v];
                int n2 = linkS[l];
                nl[ki] = n2;
                ch |= (n2 != l);
            }
            if (ch) sJ[p] = 1;
            __syncthreads();
            ki = 0;
            for (int v = tid; v < VN; v += NT, ++ki) linkS[v] = nl[ki];
            if (tid == 0) sJ[p ^ 1] = 0;
            __syncthreads();
            if (!sJ[p]) break;
        }
        for (int v = tid; v < VN; v += NT) compS[v] = linkS[compS[v]];
        __syncthreads();
    }
    __syncthreads();
    int nTree = sCnt;

    // ---- 3. tree adjacency masks (bit0:-96 bit1:+96 bit2:-1 bit3:+1) ----
    for (int v = tid; v < VN; v += NT) adjS[v] = 0;
    __syncthreads();
    for (int i = tid; i < nTree; i += NT) {
        int e = g_tredge[t * VN + i];
        int u, v; edge_uv(e, u, v);
        if (e < 9120) { atomicOr(&adjS[u], 2); atomicOr(&adjS[v], 1); }
        else { atomicOr(&adjS[u], 8); atomicOr(&adjS[v], 4); }
    }
    for (int v = tid; v < VN; v += NT) parS[v] = 0xFFFF;
    __syncthreads();

    // ---- 4. frontier BFS rooting (unique discoverer => race-free) ----
    if (tid == 0) { orderS[0] = 0; parS[0] = 0; sCur = 1; lsS[0] = 0; lsS[1] = 1; }
    __syncthreads();
    int fs = 0, fe = 1, level = 0;
    while (true) {
        for (int i = fs + tid; i < fe; i += NT) {
            int v = orderS[i];
            int m = adjS[v];
            while (m) {
                int d = __ffs(m) - 1; m &= m - 1;
                int nb = v + c_off[d];
                if (parS[nb] == 0xFFFF) {
                    parS[nb] = (unsigned short)v;
                    int pos = atomicAdd(&sCur, 1);
                    orderS[pos] = (unsigned short)nb;
                }
            }
        }
        __syncthreads();
        int nc2 = sCur;
        if (nc2 == fe) break;
        level++;
        if (tid == 0) lsS[level + 1] = nc2;
        fs = fe; fe = nc2;
        __syncthreads();
    }
    int maxd = level;

    // ---- 5. export packed structure; ew from wS (tree edges ARE grid edges) ----
    for (int pos = tid; pos < VN; pos += NT) {
        int v = orderS[pos];
        int par = parS[v];
        int m = adjS[v];
        int pardir = 0, cm = m;
        float ew = 0.f;
        if (v != 0) {
            int delta = par - v;
            pardir = (delta == -WID) ? 0 : (delta == WID) ? 1 : (delta == -1) ? 2 : 3;
            cm = m & ~(1 << pardir);
            int mn = v < par ? v : par;
            int mx = v < par ? par : v;
            int e = (mx - mn == WID) ? mn : 9120 + (mn / WID) * 95 + (mn - (mn / WID) * WID);
            ew = expf(-wS[e] * 0.5f);
        }
        g_ord32[t * VN + pos] = (unsigned)v | ((unsigned)cm << 14) | ((unsigned)pardir << 18);
        g_ew[t * VN + v] = ew;
    }
    for (int d = tid; d <= maxd + 1; d += NT) g_levelstart[t * 2048 + d] = lsS[d];
    if (tid == 0) g_maxd[t] = maxd;
}

// ---------------- fused two-filter sweep ----------------
// smem: buf f32[VN*4] @0 (147456) | ewS f32[VN] @147456 | ord32 u32[VN] @184320 | lsS int[2048] @221184
#define SWEEP_SMEM 229376

extern "C" __global__ void __launch_bounds__(256, 1)
sweep_kernel() {
    extern __shared__ unsigned char sm[];
    float* buf = (float*)sm;
    float* ewS = (float*)(sm + 147456);
    unsigned* ordS = (unsigned*)(sm + 184320);
    int* lsS = (int*)(sm + 221184);
    int g = blockIdx.x, b = blockIdx.y;
    int tid = threadIdx.x;
    const int NT = 256;

    const float* inb = g_prob + (size_t)b * NC * VN;
    for (int c = 0; c < 3; c++) {
        const float* p = inb + (size_t)(g * 3 + c) * VN;
        for (int v = tid; v < VN; v += NT) buf[v * 4 + c] = p[v];
    }
    for (int v = tid; v < VN; v += NT) buf[v * 4 + 3] = 1.f;

    for (int f = 0; f < 2; f++) {
        int t = b * 2 + f;
        int maxd = g_maxd[t];
        for (int v = tid; v < VN; v += NT) {
            ewS[v] = g_ew[t * VN + v];
            ordS[v] = g_ord32[t * VN + v];
        }
        for (int d = tid; d <= maxd + 1; d += NT) lsS[d] = g_levelstart[t * 2048 + d];
        __syncthreads();

        if (tid < 64) {
            // up sweep (pull from children via childmask)
            for (int d = maxd - 1; d >= 0; --d) {
                int s = lsS[d];
                int n = (lsS[d + 1] - s) << 2;
                for (int i = tid; i < n; i += 64) {
                    unsigned o = ordS[s + (i >> 2)];
                    int v = o & 0x3FFF;
                    int cm = (o >> 14) & 0xF;
                    int c = i & 3;
                    float acc = buf[v * 4 + c];
                    if (cm & 1) { int ch = v - WID; acc += ewS[ch] * buf[ch * 4 + c]; }
                    if (cm & 2) { int ch = v + WID; acc += ewS[ch] * buf[ch * 4 + c]; }
                    if (cm & 4) { int ch = v - 1;   acc += ewS[ch] * buf[ch * 4 + c]; }
                    if (cm & 8) { int ch = v + 1;   acc += ewS[ch] * buf[ch * 4 + c]; }
                    buf[v * 4 + c] = acc;
                }
                asm volatile("bar.sync 1, 64;" ::: "memory");
            }
            // down sweep (in place)
            for (int d = 1; d <= maxd; ++d) {
                int s = lsS[d];
                int n = (lsS[d + 1] - s) << 2;
                for (int i = tid; i < n; i += 64) {
                    unsigned o = ordS[s + (i >> 2)];
                    int v = o & 0x3FFF;
                    int pd = (o >> 18) & 3;
                    int c = i & 3;
                    int par = v + c_off[pd];
                    float w = ewS[v];
                    buf[v * 4 + c] = w * buf[par * 4 + c] + (1.f - w * w) * buf[v * 4 + c];
                }
                asm volatile("bar.sync 1, 64;" ::: "memory");
            }
        }
        __syncthreads();

        if (f == 0) {
            for (int v = tid; v < VN; v += NT) {
                float ones = buf[v * 4 + 3];
                buf[v * 4 + 0] = buf[v * 4 + 0] / ones;
                buf[v * 4 + 1] = buf[v * 4 + 1] / ones;
                buf[v * 4 + 2] = buf[v * 4 + 2] / ones;
                buf[v * 4 + 3] = 1.f;
            }
        } else {
            float* outb = g_AS + (size_t)b * NC * VN;
            for (int c = 0; c < 3; c++) {
                float* p = outb + (size_t)(g * 3 + c) * VN;
                for (int v = tid; v < VN; v += NT) p[v] = buf[v * 4 + c] / buf[v * 4 + 3];
            }
        }
    }
}

// ---------------- loss ----------------
__global__ void loss_part_kernel(const int* __restrict__ roi) {
    __shared__ double sL[256];
    __shared__ double sN[256];
    int tid = threadIdx.x, blk = blockIdx.x;
    const int total = B_ * NC * VN;
    double aL = 0.0, aN = 0.0;
    for (int idx = blk * 256 + tid; idx < total; idx += NLOSSBLK * 256) {
        int b = idx / (NC * VN);
        int r = idx - b * (NC * VN);
        int c = r / VN;
        int v = r - c * VN;
        int y = v / WID, x = v - y * WID;
        float rv = (float)roi[(size_t)b * (H0_ * H0_) + (y * 4) * H0_ + x * 4];
        aL += (double)(rv * fabsf(g_prob[idx] - g_AS[idx]));
        if (c == 0) aN += (double)rv;
    }
    sL[tid] = aL; sN[tid] = aN;
    __syncthreads();
    for (int s = 128; s > 0; s >>= 1) {
        if (tid < s) { sL[tid] += sL[tid + s]; sN[tid] += sN[tid + s]; }
        __syncthreads();
    }
    if (tid == 0) { g_partL[blk] = sL[0]; g_partN[blk] = sN[0]; }
}

__global__ void loss_final_kernel(float* out) {
    if (threadIdx.x == 0 && blockIdx.x == 0) {
        double L = 0.0, N = 0.0;
        for (int i = 0; i < NLOSSBLK; i++) { L += g_partL[i]; N += g_partN[i]; }
        double res = (N > 0.0) ? L / ((N > 1.0) ? N : 1.0) : L;
        out[0] = (float)(0.4 * res);
    }
}

// ---------------- launch ----------------
extern "C" void kernel_launch(void* const* d_in, const int* in_sizes, int n_in,
                              void* d_out, int out_size) {
    (void)in_sizes; (void)n_in; (void)out_size;
    const float* preds = (const float*)d_in[0];
    const float* low = (const float*)d_in[1];
    const float* high = (const float*)d_in[2];
    const int* roi = (const int*)d_in[3];
    float* out = (float*)d_out;

    cudaFuncSetAttribute(build_kernel, cudaFuncAttributeMaxDynamicSharedMemorySize, BUILD_SMEM);
    cudaFuncSetAttribute(sweep_kernel, cudaFuncAttributeMaxDynamicSharedMemorySize, SWEEP_SMEM);

    resize_kernel<<<(B_ * 3 * VN + 255) / 256, 256>>>(low);
    softmax_kernel<<<(B_ * VN + 255) / 256, 256>>>(preds);
    build_kernel<<<16, 1024, BUILD_SMEM>>>(high);
    dim3 gs(7, B_);
    sweep_kernel<<<gs, 256, SWEEP_SMEM>>>();
    loss_part_kernel<<<NLOSSBLK, 256>>>(roi);
    loss_final_kernel<<<1, 1>>>(out);
}